// round 11
// baseline (speedup 1.0000x reference)
#include <cuda_runtime.h>
#include <cuda_bf16.h>

// TargetedDropout inference path:
//   per channel c (last axis, C=1024), threshold = 16383-th smallest |x| over
//   the N=32768 leading entries; out = (|x| <= thr[c]) ? 0 : x.
//
// Round 10: per-thread contiguous candidate regions (2-bit column tag packed
// into bit 23; all in-window values share exponent 126) + packed per-group
// meta in [group][blk] layout -> collect scatter traffic cut ~5x and select
// reads fully coalesced. Exact histogram select; exact radix fallback.

#define C_DIM   1024
#define N_ROWS  32768
#define RANK0   16383            // int(0.5 * 32768) - 1
#define W_LO    0.64f
#define W_HI    0.71f
#define NBLK    1024             // collect blocks
#define RPB     (N_ROWS / NBLK)  // 32 rows per collect block
#define NGRP    256              // column groups (4 cols each)
#define CAPT    24               // per (group,blk) region cap (lambda = 5.69)
#define CAP     2048             // per-column total cap (mean 1457, sd 37)
#define SMALLC  288              // bin-mate capacity in select
#define MSK23   0x007FFFFFu

// [group][blk][CAPT] tagged candidates: mantissa | (col_in_group << 23). 96 MB
// reserved, ~8.4 MB touched.
__device__ unsigned g_cand[(size_t)NGRP * NBLK * CAPT];
// [group][blk] packed meta: .x = 4x8b per-col candidate counts,
//                           .y = 4x8b per-col below counts.  2 MB.
__device__ uint2    g_meta[NGRP * NBLK];
__device__ __align__(16) float g_thr[C_DIM];

// -------------------------------------------------------------------------
// Pass 1: one full read of x. Thread t exclusively owns columns 4t..4t+3
// within its block; its candidates append to ONE contiguous region.
// grid = 1024 blocks x 256 threads; each block covers 32 rows.
// -------------------------------------------------------------------------
__global__ void __launch_bounds__(256) k_collect(const float4* __restrict__ x) {
    const int t    = threadIdx.x;            // == column group id
    const int blk  = blockIdx.x;
    const int row0 = blk * RPB;

    unsigned* cp = &g_cand[((size_t)t * NBLK + blk) * CAPT];

    int n_all = 0;        // total candidates appended to region
    unsigned cnts = 0;    // 4x8b per-col candidate counts
    unsigned bels = 0;    // 4x8b per-col below counts

#define PROC1(a, u)                                                           \
    do {                                                                      \
        bels += (unsigned)((a) < W_LO) << (8 * (u));                          \
        if ((a) >= W_LO && (a) <= W_HI) {                                     \
            if (n_all < CAPT)                                                 \
                cp[n_all] = (__float_as_uint(a) & MSK23) | ((unsigned)(u) << 23); \
            n_all++;                                                          \
            cnts += 1u << (8 * (u));                                          \
        }                                                                     \
    } while (0)

#define PROC(v)                                                               \
    do {                                                                      \
        PROC1(fabsf((v).x), 0);                                               \
        PROC1(fabsf((v).y), 1);                                               \
        PROC1(fabsf((v).z), 2);                                               \
        PROC1(fabsf((v).w), 3);                                               \
    } while (0)

    #pragma unroll
    for (int j0 = 0; j0 < RPB; j0 += 4) {
        // Front-batched independent loads: MLP = 4.
        float4 v0 = x[(size_t)(row0 + j0 + 0) * 256 + t];
        float4 v1 = x[(size_t)(row0 + j0 + 1) * 256 + t];
        float4 v2 = x[(size_t)(row0 + j0 + 2) * 256 + t];
        float4 v3 = x[(size_t)(row0 + j0 + 3) * 256 + t];
        PROC(v0);
        PROC(v1);
        PROC(v2);
        PROC(v3);
    }
#undef PROC
#undef PROC1

    g_meta[t * NBLK + blk] = make_uint2(cnts, bels);
}

// -------------------------------------------------------------------------
// Pass 2: one block per column c (group g = c>>2, tag u = c&3). Thread t
// covers blocks 4t..4t+3: coalesced meta reads, shfl prefix scan, tag-filtered
// compaction into shared. Then exact selection: 4096-bin histogram on
// mantissa bits [22:11] + exact resolve among bin-mates (values share
// exponent 126, so mantissa order == value order). Fallback (rank outside
// window / any region overflow): exact 4-pass byte-wise MSD radix select.
// -------------------------------------------------------------------------
__global__ void __launch_bounds__(256) k_select(const float* __restrict__ x) {
    __shared__ unsigned sdata[CAP];     //  8 KB (mantissas)
    __shared__ int      hist[4096];     // 16 KB (fallback reuses first 256)
    __shared__ int      seg[256];
    __shared__ int      wsum[8];
    __shared__ unsigned ssmall[SMALLC];
    __shared__ int      s_smallcnt;
    __shared__ int      s_bel, s_mx;
    __shared__ int      s_fb, s_n, s_r;
    __shared__ int      s_bin, s_r2;
    __shared__ unsigned s_prefix;
    __shared__ int      s_rank;

    const int c    = blockIdx.x;
    const int g    = c >> 2;
    const unsigned u = (unsigned)(c & 3);
    const int t    = threadIdx.x;
    const int lane = t & 31;
    const int wid  = t >> 5;

    if (t == 0) { s_bel = 0; s_mx = 0; s_smallcnt = 0; }
    __syncthreads();

    int cb[4];    // this column's candidate count per covered block
    int gt[4];    // group-total candidates per covered block (overflow check)
    int sum = 0, bel = 0, mx = 0;
    #pragma unroll
    for (int r = 0; r < 4; ++r) {
        const uint2 m = g_meta[g * NBLK + (t * 4 + r)];
        cb[r] = (int)((m.x >> (8 * u)) & 255u);
        gt[r] = (int)((m.x & 255u) + ((m.x >> 8) & 255u) +
                      ((m.x >> 16) & 255u) + (m.x >> 24));
        bel  += (int)((m.y >> (8 * u)) & 255u);
        sum  += cb[r];
        if (gt[r] > mx) mx = gt[r];
    }
    atomicAdd(&s_bel, bel);
    atomicMax(&s_mx, mx);

    // Exclusive prefix scan of per-thread sums (warp shfl + 8-wide base scan).
    int v = sum;
    #pragma unroll
    for (int d = 1; d < 32; d <<= 1) {
        int o = __shfl_up_sync(0xFFFFFFFFu, v, d);
        if (lane >= d) v += o;
    }
    if (lane == 31) wsum[wid] = v;
    __syncthreads();
    if (t == 0) {
        int acc = 0;
        #pragma unroll
        for (int i = 0; i < 8; ++i) { int tmp = wsum[i]; wsum[i] = acc; acc += tmp; }
        s_n = acc;
        const int r = RANK0 - s_bel;
        s_r = r;
        s_fb = (s_mx > CAPT || acc > CAP || r < 0 || r >= acc) ? 1 : 0;
    }
    __syncthreads();

    const int excl = wsum[wid] + v - sum;    // this thread's base offset
    const int n = s_n;
    const int r = s_r;

    if (!s_fb) {
        // Compaction: read each covered region, keep entries tagged u
        // (row order preserved -> deterministic layout).
        {
            int o = excl;
            #pragma unroll
            for (int rr = 0; rr < 4; ++rr) {
                const unsigned* src =
                    &g_cand[((size_t)g * NBLK + (t * 4 + rr)) * CAPT];
                const int m = gt[rr];
                for (int j = 0; j < m; ++j) {
                    const unsigned w = src[j];
                    if ((w >> 23) == u) sdata[o++] = w & MSK23;
                }
            }
        }
        for (int i = t; i < 4096; i += 256) hist[i] = 0;
        __syncthreads();

        for (int i = t; i < n; i += 256)
            atomicAdd(&hist[sdata[i] >> 11], 1);
        __syncthreads();

        // segmented prefix: 256 segments of 16 bins
        int s = 0;
        #pragma unroll
        for (int q = 0; q < 16; ++q) s += hist[t * 16 + q];
        seg[t] = s;
        __syncthreads();

        if (t == 0) {
            int cum = 0, si = 0;
            while (cum + seg[si] <= r) { cum += seg[si]; ++si; }
            int b = si * 16;
            while (cum + hist[b] <= r) { cum += hist[b]; ++b; }
            s_bin = b;
            s_r2  = r - cum;
        }
        __syncthreads();

        const unsigned bsel = (unsigned)s_bin;
        for (int i = t; i < n; i += 256) {
            if ((sdata[i] >> 11) == bsel) {
                int p = atomicAdd(&s_smallcnt, 1);
                if (p < SMALLC) ssmall[p] = sdata[i];
            }
        }
        __syncthreads();

        if (t == 0) {
            int m = s_smallcnt;
            if (m > SMALLC) {
                s_fb = 1;                      // pathological: redo exactly
            } else {
                const int r2 = s_r2;
                unsigned ans = 0;
                for (int i = 0; i < m; ++i) {
                    unsigned vv = ssmall[i];
                    int less = 0, eq = 0;
                    for (int j = 0; j < m; ++j) {
                        less += (ssmall[j] < vv);
                        eq   += (ssmall[j] == vv);
                    }
                    if (less <= r2 && r2 < less + eq) { ans = vv; break; }
                }
                g_thr[c] = __uint_as_float(ans | (126u << 23));
            }
        }
        __syncthreads();
    }

    if (s_fb) {
        // Exact MSD radix select over the whole column (4 x 8-bit passes).
        if (t == 0) { s_prefix = 0; s_rank = RANK0; }
        for (int shift = 24; shift >= 0; shift -= 8) {
            hist[t] = 0;                       // only 256 bins used here
            __syncthreads();
            const unsigned pfx = s_prefix;
            const int hs = shift + 8;
            for (int row = t; row < N_ROWS; row += 256) {
                unsigned key = __float_as_uint(fabsf(x[(size_t)row * C_DIM + c]));
                bool ok = (hs >= 32) || ((key >> hs) == (pfx >> hs));
                if (ok) atomicAdd(&hist[(key >> shift) & 255], 1);
            }
            __syncthreads();
            if (t == 0) {
                int cum = 0, b = 0;
                while (cum + hist[b] <= s_rank) { cum += hist[b]; ++b; }
                s_rank  -= cum;
                s_prefix |= ((unsigned)b) << shift;
            }
            __syncthreads();
        }
        if (t == 0) g_thr[c] = __uint_as_float(s_prefix);
    }
}

// -------------------------------------------------------------------------
// Pass 3: streaming mask. blockDim must be 256 so each thread's column group
// (threadIdx.x) is loop-invariant -> threshold float4 hoisted out of the loop.
// -------------------------------------------------------------------------
__global__ void __launch_bounds__(256) k_mask(const float4* __restrict__ x,
                                              float4* __restrict__ out,
                                              int n4) {
    const float4 thr = reinterpret_cast<const float4*>(g_thr)[threadIdx.x];
    const int stride = gridDim.x * blockDim.x;   // multiple of 256
    for (int i = blockIdx.x * blockDim.x + threadIdx.x; i < n4; i += stride) {
        float4 v = x[i];
        float4 o;
        o.x = (fabsf(v.x) <= thr.x) ? 0.0f : v.x;
        o.y = (fabsf(v.y) <= thr.y) ? 0.0f : v.y;
        o.z = (fabsf(v.z) <= thr.z) ? 0.0f : v.z;
        o.w = (fabsf(v.w) <= thr.w) ? 0.0f : v.w;
        out[i] = o;
    }
}

extern "C" void kernel_launch(void* const* d_in, const int* in_sizes, int n_in,
                              void* d_out, int out_size) {
    const float* x = (const float*)d_in[0];
    float* out     = (float*)d_out;
    const int n4   = out_size / 4;               // 8,388,608 float4s

    k_collect<<<NBLK, 256>>>((const float4*)x);
    k_select <<<C_DIM, 256>>>(x);
    k_mask   <<<8192, 256>>>((const float4*)x, (float4*)out, n4);
}

// round 12
// speedup vs baseline: 1.2400x; 1.2400x over previous
#include <cuda_runtime.h>
#include <cuda_bf16.h>

// TargetedDropout inference path:
//   per channel c (last axis, C=1024), threshold = 16383-th smallest |x| over
//   the N=32768 leading entries; out = (|x| <= thr[c]) ? 0 : x.
//
// Round 11: collect unchanged (per-thread contiguous tagged regions, 36.6us).
// Select restructured: one block per 4-column GROUP -> regions read once,
// no tag-filter waste, packed dual 16-bit shfl scans, four sequential exact
// histogram selections in shared memory. Exact radix fallback per column.

#define C_DIM   1024
#define N_ROWS  32768
#define RANK0   16383            // int(0.5 * 32768) - 1
#define W_LO    0.64f
#define W_HI    0.71f
#define NBLK    1024             // collect blocks
#define RPB     (N_ROWS / NBLK)  // 32 rows per collect block
#define NGRP    256              // column groups (4 cols each)
#define CAPT    24               // per (group,blk) region cap (lambda = 5.69)
#define CAPC    1664             // per-column shared capacity (mean 1457, +5.5 sd)
#define SMALLC  288              // bin-mate capacity in select
#define MSK23   0x007FFFFFu

// [group][blk][CAPT] tagged candidates: mantissa | (col_in_group << 23).
__device__ unsigned g_cand[(size_t)NGRP * NBLK * CAPT];
// [group][blk] packed meta: .x = 4x8b per-col candidate counts,
//                           .y = 4x8b per-col below counts.  2 MB.
__device__ uint2    g_meta[NGRP * NBLK];
__device__ __align__(16) float g_thr[C_DIM];

// -------------------------------------------------------------------------
// Pass 1: one full read of x. Thread t exclusively owns columns 4t..4t+3
// within its block; its candidates append to ONE contiguous region.
// grid = 1024 blocks x 256 threads; each block covers 32 rows.
// -------------------------------------------------------------------------
__global__ void __launch_bounds__(256) k_collect(const float4* __restrict__ x) {
    const int t    = threadIdx.x;            // == column group id
    const int blk  = blockIdx.x;
    const int row0 = blk * RPB;

    unsigned* cp = &g_cand[((size_t)t * NBLK + blk) * CAPT];

    int n_all = 0;        // total candidates appended to region
    unsigned cnts = 0;    // 4x8b per-col candidate counts
    unsigned bels = 0;    // 4x8b per-col below counts

#define PROC1(a, u)                                                           \
    do {                                                                      \
        bels += (unsigned)((a) < W_LO) << (8 * (u));                          \
        if ((a) >= W_LO && (a) <= W_HI) {                                     \
            if (n_all < CAPT)                                                 \
                cp[n_all] = (__float_as_uint(a) & MSK23) | ((unsigned)(u) << 23); \
            n_all++;                                                          \
            cnts += 1u << (8 * (u));                                          \
        }                                                                     \
    } while (0)

#define PROC(v)                                                               \
    do {                                                                      \
        PROC1(fabsf((v).x), 0);                                               \
        PROC1(fabsf((v).y), 1);                                               \
        PROC1(fabsf((v).z), 2);                                               \
        PROC1(fabsf((v).w), 3);                                               \
    } while (0)

    #pragma unroll
    for (int j0 = 0; j0 < RPB; j0 += 4) {
        // Front-batched independent loads: MLP = 4.
        float4 v0 = x[(size_t)(row0 + j0 + 0) * 256 + t];
        float4 v1 = x[(size_t)(row0 + j0 + 1) * 256 + t];
        float4 v2 = x[(size_t)(row0 + j0 + 2) * 256 + t];
        float4 v3 = x[(size_t)(row0 + j0 + 3) * 256 + t];
        PROC(v0);
        PROC(v1);
        PROC(v2);
        PROC(v3);
    }
#undef PROC
#undef PROC1

    g_meta[t * NBLK + blk] = make_uint2(cnts, bels);
}

// -------------------------------------------------------------------------
// Pass 2: one block per GROUP g (columns 4g..4g+3). Thread t covers regions
// 4t..4t+3: coalesced meta reads, two packed 16-bit shfl scans give all four
// per-column offsets, one pass over the regions dispatches entries into four
// per-column shared arrays. Then four sequential exact selections: 4096-bin
// histogram on mantissa bits [22:11] + exact resolve among bin-mates (all
// values share exponent 126, so mantissa order == value order).
// Fallback (rank outside window / any overflow): exact radix select.
// -------------------------------------------------------------------------
__global__ void __launch_bounds__(256) k_select(const float* __restrict__ x) {
    __shared__ unsigned sdata[4][CAPC];   // 26 KB
    __shared__ int      hist[4096];       // 16 KB (fallback reuses first 256)
    __shared__ int      seg[256];
    __shared__ int      wsumA[8], wsumB[8];
    __shared__ unsigned ssmall[SMALLC];
    __shared__ int      s_smallcnt;
    __shared__ int      s_bel[4], s_n[4], s_r[4], s_fb[4];
    __shared__ int      s_any_over;
    __shared__ int      s_totA, s_totB;
    __shared__ int      s_bin, s_r2;
    __shared__ unsigned s_prefix;
    __shared__ int      s_rank;

    const int g    = blockIdx.x;
    const int t    = threadIdx.x;
    const int lane = t & 31;
    const int wid  = t >> 5;

    if (t < 4) { s_bel[t] = 0; s_fb[t] = 0; }
    if (t == 0) s_any_over = 0;
    __syncthreads();

    // Meta for my 4 regions (coalesced: thread t reads 32 consecutive bytes).
    unsigned mcnt[4];
    int      mtot[4];          // clamped region totals (safe read bound)
    int tc0 = 0, tc1 = 0, tc2 = 0, tc3 = 0;
    int bel0 = 0, bel1 = 0, bel2 = 0, bel3 = 0;
    bool over = false;
    #pragma unroll
    for (int rr = 0; rr < 4; ++rr) {
        const uint2 m = g_meta[g * NBLK + (t * 4 + rr)];
        mcnt[rr] = m.x;
        const int b0 = (int)(m.x & 255u),        b1 = (int)((m.x >> 8) & 255u);
        const int b2 = (int)((m.x >> 16) & 255u), b3 = (int)(m.x >> 24);
        const int gt = b0 + b1 + b2 + b3;
        if (gt > CAPT) over = true;
        mtot[rr] = (gt > CAPT) ? CAPT : gt;
        tc0 += b0;  tc1 += b1;  tc2 += b2;  tc3 += b3;
        bel0 += (int)(m.y & 255u);         bel1 += (int)((m.y >> 8) & 255u);
        bel2 += (int)((m.y >> 16) & 255u); bel3 += (int)(m.y >> 24);
    }
    if (over) s_any_over = 1;
    atomicAdd(&s_bel[0], bel0);  atomicAdd(&s_bel[1], bel1);
    atomicAdd(&s_bel[2], bel2);  atomicAdd(&s_bel[3], bel3);

    // Dual packed 16-bit exclusive scans: A = col0 | col2<<16, B = col1 | col3<<16.
    // Per-column cumulative <= ~1700 << 65536, so halves never carry.
    const int A = tc0 | (tc2 << 16);
    const int B = tc1 | (tc3 << 16);
    int iA = A, iB = B;
    #pragma unroll
    for (int d = 1; d < 32; d <<= 1) {
        int oA = __shfl_up_sync(0xFFFFFFFFu, iA, d);
        int oB = __shfl_up_sync(0xFFFFFFFFu, iB, d);
        if (lane >= d) { iA += oA; iB += oB; }
    }
    if (lane == 31) { wsumA[wid] = iA; wsumB[wid] = iB; }
    __syncthreads();
    if (t == 0) {
        int aA = 0, aB = 0;
        #pragma unroll
        for (int i = 0; i < 8; ++i) {
            int ta = wsumA[i], tb = wsumB[i];
            wsumA[i] = aA; wsumB[i] = aB;
            aA += ta; aB += tb;
        }
        s_totA = aA;  s_totB = aB;
    }
    __syncthreads();

    if (t < 4) {
        const int n = (t == 0) ? (s_totA & 0xFFFF) :
                      (t == 1) ? (s_totB & 0xFFFF) :
                      (t == 2) ? (s_totA >> 16)    : (s_totB >> 16);
        const int r = RANK0 - s_bel[t];
        s_n[t] = n;
        s_r[t] = r;
        s_fb[t] = (s_any_over || n > CAPC || r < 0 || r >= n) ? 1 : 0;
    }

    const int eA = wsumA[wid] + iA - A;
    const int eB = wsumB[wid] + iB - B;
    int cur[4];
    cur[0] = eA & 0xFFFF;  cur[2] = eA >> 16;
    cur[1] = eB & 0xFFFF;  cur[3] = eB >> 16;

    // Dispatch my regions' entries into the four column arrays (read ONCE).
    #pragma unroll
    for (int rr = 0; rr < 4; ++rr) {
        const unsigned* src = &g_cand[((size_t)g * NBLK + (t * 4 + rr)) * CAPT];
        const int m = mtot[rr];
        for (int j = 0; j < m; ++j) {
            const unsigned w = src[j];
            const int u = (int)(w >> 23);
            const int o = cur[u]++;
            if (o < CAPC) sdata[u][o] = w & MSK23;
        }
    }
    __syncthreads();

    // Four sequential exact selections over shared data.
    for (int u = 0; u < 4; ++u) {
        if (!s_fb[u]) {
            const int n = s_n[u];
            const int r = s_r[u];
            const unsigned* sd = sdata[u];

            for (int i = t; i < 4096; i += 256) hist[i] = 0;
            if (t == 0) s_smallcnt = 0;
            __syncthreads();

            for (int i = t; i < n; i += 256)
                atomicAdd(&hist[sd[i] >> 11], 1);
            __syncthreads();

            int s = 0;
            #pragma unroll
            for (int q = 0; q < 16; ++q) s += hist[t * 16 + q];
            seg[t] = s;
            __syncthreads();

            if (t == 0) {
                int cum = 0, si = 0;
                while (cum + seg[si] <= r) { cum += seg[si]; ++si; }
                int b = si * 16;
                while (cum + hist[b] <= r) { cum += hist[b]; ++b; }
                s_bin = b;
                s_r2  = r - cum;
            }
            __syncthreads();

            const unsigned bsel = (unsigned)s_bin;
            for (int i = t; i < n; i += 256) {
                if ((sd[i] >> 11) == bsel) {
                    int p = atomicAdd(&s_smallcnt, 1);
                    if (p < SMALLC) ssmall[p] = sd[i];
                }
            }
            __syncthreads();

            if (t == 0) {
                const int m = s_smallcnt;
                if (m > SMALLC) {
                    s_fb[u] = 1;                 // pathological: redo exactly
                } else {
                    const int r2 = s_r2;
                    unsigned ans = 0;
                    for (int i = 0; i < m; ++i) {
                        unsigned vv = ssmall[i];
                        int less = 0, eq = 0;
                        for (int j = 0; j < m; ++j) {
                            less += (ssmall[j] < vv);
                            eq   += (ssmall[j] == vv);
                        }
                        if (less <= r2 && r2 < less + eq) { ans = vv; break; }
                    }
                    g_thr[g * 4 + u] = __uint_as_float(ans | (126u << 23));
                }
            }
            __syncthreads();
        }
    }

    // Exact MSD radix-select fallback for any flagged column (4 x 8-bit passes).
    for (int u = 0; u < 4; ++u) {
        if (s_fb[u]) {
            const int c = g * 4 + u;
            if (t == 0) { s_prefix = 0; s_rank = RANK0; }
            for (int shift = 24; shift >= 0; shift -= 8) {
                hist[t] = 0;                     // only 256 bins used here
                __syncthreads();
                const unsigned pfx = s_prefix;
                const int hs = shift + 8;
                for (int row = t; row < N_ROWS; row += 256) {
                    unsigned key = __float_as_uint(fabsf(x[(size_t)row * C_DIM + c]));
                    bool ok = (hs >= 32) || ((key >> hs) == (pfx >> hs));
                    if (ok) atomicAdd(&hist[(key >> shift) & 255], 1);
                }
                __syncthreads();
                if (t == 0) {
                    int cum = 0, b = 0;
                    while (cum + hist[b] <= s_rank) { cum += hist[b]; ++b; }
                    s_rank  -= cum;
                    s_prefix |= ((unsigned)b) << shift;
                }
                __syncthreads();
            }
            if (t == 0) g_thr[c] = __uint_as_float(s_prefix);
            __syncthreads();
        }
    }
}

// -------------------------------------------------------------------------
// Pass 3: streaming mask. blockDim must be 256 so each thread's column group
// (threadIdx.x) is loop-invariant -> threshold float4 hoisted out of the loop.
// -------------------------------------------------------------------------
__global__ void __launch_bounds__(256) k_mask(const float4* __restrict__ x,
                                              float4* __restrict__ out,
                                              int n4) {
    const float4 thr = reinterpret_cast<const float4*>(g_thr)[threadIdx.x];
    const int stride = gridDim.x * blockDim.x;   // multiple of 256
    for (int i = blockIdx.x * blockDim.x + threadIdx.x; i < n4; i += stride) {
        float4 v = x[i];
        float4 o;
        o.x = (fabsf(v.x) <= thr.x) ? 0.0f : v.x;
        o.y = (fabsf(v.y) <= thr.y) ? 0.0f : v.y;
        o.z = (fabsf(v.z) <= thr.z) ? 0.0f : v.z;
        o.w = (fabsf(v.w) <= thr.w) ? 0.0f : v.w;
        out[i] = o;
    }
}

extern "C" void kernel_launch(void* const* d_in, const int* in_sizes, int n_in,
                              void* d_out, int out_size) {
    const float* x = (const float*)d_in[0];
    float* out     = (float*)d_out;
    const int n4   = out_size / 4;               // 8,388,608 float4s

    k_collect<<<NBLK, 256>>>((const float4*)x);
    k_select <<<NGRP, 256>>>(x);
    k_mask   <<<8192, 256>>>((const float4*)x, (float4*)out, n4);
}

// round 13
// speedup vs baseline: 1.4576x; 1.1755x over previous
#include <cuda_runtime.h>
#include <cuda_bf16.h>

// TargetedDropout inference path:
//   per channel c (last axis, C=1024), threshold = 16383-th smallest |x| over
//   the N=32768 leading entries; out = (|x| <= thr[c]) ? 0 : x.
//
// Round 12: select's four per-column selections now run CONCURRENTLY via
// packed 16-bit dual histograms (2048 bins) + packed shfl scans + parallel
// rank-segment location. No serial t==0 scans remain. Collect and mask
// unchanged. Exact radix fallback per column retained.

#define C_DIM   1024
#define N_ROWS  32768
#define RANK0   16383            // int(0.5 * 32768) - 1
#define W_LO    0.64f
#define W_HI    0.71f
#define NBLK    1024             // collect blocks
#define RPB     (N_ROWS / NBLK)  // 32 rows per collect block
#define NGRP    256              // column groups (4 cols each)
#define CAPT    24               // per (group,blk) region cap (lambda = 5.69)
#define CAPC    1664             // per-column shared capacity (mean 1457, +5.5 sd)
#define SMALLC  96               // bin-mate capacity (Poisson(~5) at 2048 bins)
#define MSK23   0x007FFFFFu

// [group][blk][CAPT] tagged candidates: mantissa | (col_in_group << 23).
__device__ unsigned g_cand[(size_t)NGRP * NBLK * CAPT];
// [group][blk] packed meta: .x = 4x8b per-col candidate counts,
//                           .y = 4x8b per-col below counts.  2 MB.
__device__ uint2    g_meta[NGRP * NBLK];
__device__ __align__(16) float g_thr[C_DIM];

// -------------------------------------------------------------------------
// Pass 1: one full read of x. Thread t exclusively owns columns 4t..4t+3
// within its block; its candidates append to ONE contiguous region.
// grid = 1024 blocks x 256 threads; each block covers 32 rows.
// -------------------------------------------------------------------------
__global__ void __launch_bounds__(256) k_collect(const float4* __restrict__ x) {
    const int t    = threadIdx.x;            // == column group id
    const int blk  = blockIdx.x;
    const int row0 = blk * RPB;

    unsigned* cp = &g_cand[((size_t)t * NBLK + blk) * CAPT];

    int n_all = 0;        // total candidates appended to region
    unsigned cnts = 0;    // 4x8b per-col candidate counts
    unsigned bels = 0;    // 4x8b per-col below counts

#define PROC1(a, u)                                                           \
    do {                                                                      \
        bels += (unsigned)((a) < W_LO) << (8 * (u));                          \
        if ((a) >= W_LO && (a) <= W_HI) {                                     \
            if (n_all < CAPT)                                                 \
                cp[n_all] = (__float_as_uint(a) & MSK23) | ((unsigned)(u) << 23); \
            n_all++;                                                          \
            cnts += 1u << (8 * (u));                                          \
        }                                                                     \
    } while (0)

#define PROC(v)                                                               \
    do {                                                                      \
        PROC1(fabsf((v).x), 0);                                               \
        PROC1(fabsf((v).y), 1);                                               \
        PROC1(fabsf((v).z), 2);                                               \
        PROC1(fabsf((v).w), 3);                                               \
    } while (0)

    #pragma unroll
    for (int j0 = 0; j0 < RPB; j0 += 4) {
        // Front-batched independent loads: MLP = 4.
        float4 v0 = x[(size_t)(row0 + j0 + 0) * 256 + t];
        float4 v1 = x[(size_t)(row0 + j0 + 1) * 256 + t];
        float4 v2 = x[(size_t)(row0 + j0 + 2) * 256 + t];
        float4 v3 = x[(size_t)(row0 + j0 + 3) * 256 + t];
        PROC(v0);
        PROC(v1);
        PROC(v2);
        PROC(v3);
    }
#undef PROC
#undef PROC1

    g_meta[t * NBLK + blk] = make_uint2(cnts, bels);
}

// -------------------------------------------------------------------------
// Pass 2: one block per GROUP g (columns 4g..4g+3). Coalesced meta reads,
// packed 16-bit shfl scans for per-column dispatch offsets, one region pass
// fills four per-column shared arrays. Then ALL FOUR selections concurrently:
// packed dual 2048-bin histograms (bins = mantissa bits [22:12]; values share
// exponent 126 so mantissa order == value order), packed segment scans,
// parallel rank-segment location, shared bin-mate resolve in threads 0..3.
// Fallback (rank outside window / any overflow): exact radix select.
// -------------------------------------------------------------------------
__global__ void __launch_bounds__(256) k_select(const float* __restrict__ x) {
    __shared__ unsigned sdata[4][CAPC];   // 26.6 KB
    __shared__ int      histA[2048];      // col0 lo16 | col2 hi16
    __shared__ int      histB[2048];      // col1 lo16 | col3 hi16
    __shared__ unsigned ssmall[4][SMALLC];
    __shared__ int      s_smc[4];
    __shared__ int      s_bel[4], s_n[4], s_r[4], s_fb[4];
    __shared__ int      s_bin[4], s_r2[4];
    __shared__ int      s_any_over;
    __shared__ int      wsumA[8], wsumB[8];
    __shared__ unsigned s_prefix;
    __shared__ int      s_rank;

    const int g    = blockIdx.x;
    const int t    = threadIdx.x;
    const int lane = t & 31;
    const int wid  = t >> 5;

    if (t < 4) { s_bel[t] = 0; s_fb[t] = 0; s_smc[t] = 0; }
    if (t == 0) s_any_over = 0;
    __syncthreads();

    // ---- meta for my 4 regions (coalesced 32B/thread) ----
    int mtot[4];          // clamped region totals (safe read bound)
    int tc0 = 0, tc1 = 0, tc2 = 0, tc3 = 0;
    int bel0 = 0, bel1 = 0, bel2 = 0, bel3 = 0;
    bool over = false;
    #pragma unroll
    for (int rr = 0; rr < 4; ++rr) {
        const uint2 m = g_meta[g * NBLK + (t * 4 + rr)];
        const int b0 = (int)(m.x & 255u),         b1 = (int)((m.x >> 8) & 255u);
        const int b2 = (int)((m.x >> 16) & 255u), b3 = (int)(m.x >> 24);
        const int gt = b0 + b1 + b2 + b3;
        if (gt > CAPT) over = true;
        mtot[rr] = (gt > CAPT) ? CAPT : gt;
        tc0 += b0;  tc1 += b1;  tc2 += b2;  tc3 += b3;
        bel0 += (int)(m.y & 255u);         bel1 += (int)((m.y >> 8) & 255u);
        bel2 += (int)((m.y >> 16) & 255u); bel3 += (int)(m.y >> 24);
    }
    if (over) s_any_over = 1;
    atomicAdd(&s_bel[0], bel0);  atomicAdd(&s_bel[1], bel1);
    atomicAdd(&s_bel[2], bel2);  atomicAdd(&s_bel[3], bel3);

    // ---- packed 16-bit exclusive scans for dispatch offsets ----
    const int A = tc0 | (tc2 << 16);
    const int B = tc1 | (tc3 << 16);
    int iA = A, iB = B;
    #pragma unroll
    for (int d = 1; d < 32; d <<= 1) {
        int oA = __shfl_up_sync(0xFFFFFFFFu, iA, d);
        int oB = __shfl_up_sync(0xFFFFFFFFu, iB, d);
        if (lane >= d) { iA += oA; iB += oB; }
    }
    if (lane == 31) { wsumA[wid] = iA; wsumB[wid] = iB; }
    __syncthreads();
    if (t == 0) {
        int aA = 0, aB = 0;
        #pragma unroll
        for (int i = 0; i < 8; ++i) {
            int ta = wsumA[i], tb = wsumB[i];
            wsumA[i] = aA; wsumB[i] = aB;
            aA += ta; aB += tb;
        }
        s_n[0] = aA & 0xFFFF;  s_n[2] = aA >> 16;
        s_n[1] = aB & 0xFFFF;  s_n[3] = aB >> 16;
    }
    __syncthreads();

    if (t < 4) {
        const int n = s_n[t];
        const int r = RANK0 - s_bel[t];
        s_r[t] = r;
        s_fb[t] = (s_any_over || n > CAPC || r < 0 || r >= n) ? 1 : 0;
    }

    const int eA = wsumA[wid] + iA - A;
    const int eB = wsumB[wid] + iB - B;
    int cur[4];
    cur[0] = eA & 0xFFFF;  cur[2] = eA >> 16;
    cur[1] = eB & 0xFFFF;  cur[3] = eB >> 16;

    // ---- dispatch my regions' entries into the four column arrays ----
    #pragma unroll
    for (int rr = 0; rr < 4; ++rr) {
        const unsigned* src = &g_cand[((size_t)g * NBLK + (t * 4 + rr)) * CAPT];
        const int m = mtot[rr];
        for (int j = 0; j < m; ++j) {
            const unsigned w = src[j];
            const int u = (int)(w >> 23);
            const int o = cur[u]++;
            if (o < CAPC) sdata[u][o] = w & MSK23;
        }
    }

    // ---- zero packed histograms ----
    #pragma unroll
    for (int q = 0; q < 8; ++q) { histA[t + q * 256] = 0; histB[t + q * 256] = 0; }
    __syncthreads();

    // ---- one histogram pass covering all four columns (packed adds) ----
    {
        const int nu0 = s_fb[0] ? 0 : s_n[0];
        const int nu1 = s_fb[1] ? 0 : s_n[1];
        const int nu2 = s_fb[2] ? 0 : s_n[2];
        const int nu3 = s_fb[3] ? 0 : s_n[3];
        for (int i = t; i < nu0; i += 256) atomicAdd(&histA[sdata[0][i] >> 12], 1);
        for (int i = t; i < nu1; i += 256) atomicAdd(&histB[sdata[1][i] >> 12], 1);
        for (int i = t; i < nu2; i += 256) atomicAdd(&histA[sdata[2][i] >> 12], 1 << 16);
        for (int i = t; i < nu3; i += 256) atomicAdd(&histB[sdata[3][i] >> 12], 1 << 16);
    }
    __syncthreads();

    // ---- packed segment sums (8 bins each) + packed scans ----
    int sA = 0, sB = 0;
    #pragma unroll
    for (int q = 0; q < 8; ++q) { sA += histA[t * 8 + q]; sB += histB[t * 8 + q]; }
    int jA = sA, jB = sB;
    #pragma unroll
    for (int d = 1; d < 32; d <<= 1) {
        int oA = __shfl_up_sync(0xFFFFFFFFu, jA, d);
        int oB = __shfl_up_sync(0xFFFFFFFFu, jB, d);
        if (lane >= d) { jA += oA; jB += oB; }
    }
    if (lane == 31) { wsumA[wid] = jA; wsumB[wid] = jB; }
    __syncthreads();
    if (t == 0) {
        int aA = 0, aB = 0;
        #pragma unroll
        for (int i = 0; i < 8; ++i) {
            int ta = wsumA[i], tb = wsumB[i];
            wsumA[i] = aA; wsumB[i] = aB;
            aA += ta; aB += tb;
        }
    }
    __syncthreads();
    const int exA = wsumA[wid] + jA - sA;   // packed exclusive prefixes
    const int exB = wsumB[wid] + jB - sB;

    // ---- parallel rank-segment location: the one thread whose segment
    //      contains r walks its <=8 bins. Four columns concurrently. ----
#define FIND(uu, HH, ex, sg, SH)                                              \
    do {                                                                      \
        if (!s_fb[uu]) {                                                      \
            const int r_ = s_r[uu];                                           \
            const int e_ = ((ex) >> (SH)) & 0xFFFF;                           \
            const int g_ = ((sg) >> (SH)) & 0xFFFF;                           \
            if (e_ <= r_ && r_ < e_ + g_) {                                   \
                int cum = e_, b = t * 8;                                      \
                while (cum + (int)(((unsigned)HH[b] >> (SH)) & 0xFFFFu) <= r_) { \
                    cum += (int)(((unsigned)HH[b] >> (SH)) & 0xFFFFu);        \
                    ++b;                                                      \
                }                                                             \
                s_bin[uu] = b;                                                \
                s_r2[uu]  = r_ - cum;                                         \
            }                                                                 \
        }                                                                     \
    } while (0)
    FIND(0, histA, exA, sA, 0);
    FIND(1, histB, exB, sB, 0);
    FIND(2, histA, exA, sA, 16);
    FIND(3, histB, exB, sB, 16);
#undef FIND
    __syncthreads();

    // ---- bin-mate collection: one pass over each column's shared array ----
    #pragma unroll
    for (int u = 0; u < 4; ++u) {
        if (!s_fb[u]) {
            const int n = s_n[u];
            const unsigned bsel = (unsigned)s_bin[u];
            const unsigned* sd = sdata[u];
            for (int i = t; i < n; i += 256) {
                if ((sd[i] >> 12) == bsel) {
                    int p = atomicAdd(&s_smc[u], 1);
                    if (p < SMALLC) ssmall[u][p] = sd[i];
                }
            }
        }
    }
    __syncthreads();

    // ---- resolve: threads 0..3 handle one column each (m ~ 5) ----
    if (t < 4 && !s_fb[t]) {
        const int m = s_smc[t];
        if (m > SMALLC) {
            s_fb[t] = 1;                       // pathological: redo exactly
        } else {
            const int r2 = s_r2[t];
            unsigned ans = 0;
            for (int i = 0; i < m; ++i) {
                unsigned vv = ssmall[t][i];
                int less = 0, eq = 0;
                for (int j = 0; j < m; ++j) {
                    less += (ssmall[t][j] < vv);
                    eq   += (ssmall[t][j] == vv);
                }
                if (less <= r2 && r2 < less + eq) { ans = vv; break; }
            }
            g_thr[g * 4 + t] = __uint_as_float(ans | (126u << 23));
        }
    }
    __syncthreads();

    // ---- exact MSD radix-select fallback for any flagged column ----
    for (int u = 0; u < 4; ++u) {
        if (s_fb[u]) {
            const int c = g * 4 + u;
            if (t == 0) { s_prefix = 0; s_rank = RANK0; }
            for (int shift = 24; shift >= 0; shift -= 8) {
                histA[t] = 0;                  // only 256 bins used here
                __syncthreads();
                const unsigned pfx = s_prefix;
                const int hs = shift + 8;
                for (int row = t; row < N_ROWS; row += 256) {
                    unsigned key = __float_as_uint(fabsf(x[(size_t)row * C_DIM + c]));
                    bool ok = (hs >= 32) || ((key >> hs) == (pfx >> hs));
                    if (ok) atomicAdd(&histA[(key >> shift) & 255], 1);
                }
                __syncthreads();
                if (t == 0) {
                    int cum = 0, b = 0;
                    while (cum + histA[b] <= s_rank) { cum += histA[b]; ++b; }
                    s_rank  -= cum;
                    s_prefix |= ((unsigned)b) << shift;
                }
                __syncthreads();
            }
            if (t == 0) g_thr[c] = __uint_as_float(s_prefix);
            __syncthreads();
        }
    }
}

// -------------------------------------------------------------------------
// Pass 3: streaming mask. blockDim must be 256 so each thread's column group
// (threadIdx.x) is loop-invariant -> threshold float4 hoisted out of the loop.
// -------------------------------------------------------------------------
__global__ void __launch_bounds__(256) k_mask(const float4* __restrict__ x,
                                              float4* __restrict__ out,
                                              int n4) {
    const float4 thr = reinterpret_cast<const float4*>(g_thr)[threadIdx.x];
    const int stride = gridDim.x * blockDim.x;   // multiple of 256
    for (int i = blockIdx.x * blockDim.x + threadIdx.x; i < n4; i += stride) {
        float4 v = x[i];
        float4 o;
        o.x = (fabsf(v.x) <= thr.x) ? 0.0f : v.x;
        o.y = (fabsf(v.y) <= thr.y) ? 0.0f : v.y;
        o.z = (fabsf(v.z) <= thr.z) ? 0.0f : v.z;
        o.w = (fabsf(v.w) <= thr.w) ? 0.0f : v.w;
        out[i] = o;
    }
}

extern "C" void kernel_launch(void* const* d_in, const int* in_sizes, int n_in,
                              void* d_out, int out_size) {
    const float* x = (const float*)d_in[0];
    float* out     = (float*)d_out;
    const int n4   = out_size / 4;               // 8,388,608 float4s

    k_collect<<<NBLK, 256>>>((const float4*)x);
    k_select <<<NGRP, 256>>>(x);
    k_mask   <<<8192, 256>>>((const float4*)x, (float4*)out, n4);
}